// round 1
// baseline (speedup 1.0000x reference)
#include <cuda_runtime.h>
#include <math.h>

// Problem dims
#define BB 256
#define TT 512
#define HH 256
#define G3 768          // 3*H
#define INDIM 75
#define BT (BB*TT)      // 131072

// ---------------- scratch (device globals; no allocations allowed) ---------
__device__ float g_xg[(size_t)BB * TT * G3];     // 402 MB: input-gate preactivations (reused per layer)
__device__ float g_out0[(size_t)BB * TT * HH];   // 134 MB: layer-0 hidden states (doubles as h history)
__device__ float g_hbuf[2][BB * HH];             // layer-1 h ping-pong
__device__ unsigned g_cnt[TT];                   // per-step arrival counters

// ---------------- tiny kernel: reset barrier counters ----------------------
__global__ void zero_cnt_kernel() {
    int t = threadIdx.x;
    if (t < TT) g_cnt[t] = 0u;
}

// ---------------- GEMM: C[M,N] = A[M,K] @ W[N,K]^T + bias[N] ----------------
// BM=128, BN=64, BK=8, 256 threads, thread tile 8x4.
#define GBM 128
#define GBN 64
#define GBK 8
__global__ __launch_bounds__(256) void gemm_bias_kernel(
    const float* __restrict__ A, const float* __restrict__ W,
    const float* __restrict__ bias, float* __restrict__ C,
    int M, int N, int K)
{
    __shared__ float As[GBK][GBM];
    __shared__ float Bs[GBK][GBN + 4];

    int tid = threadIdx.x;
    int tx = tid & 15;        // n: 16 * 4 = 64
    int ty = tid >> 4;        // m: 16 * 8 = 128
    int m0 = blockIdx.x * GBM;
    int n0 = blockIdx.y * GBN;

    float acc[8][4];
#pragma unroll
    for (int i = 0; i < 8; i++)
#pragma unroll
        for (int j = 0; j < 4; j++) acc[i][j] = 0.f;

    for (int k0 = 0; k0 < K; k0 += GBK) {
        // A tile: 128x8
#pragma unroll
        for (int i = 0; i < 4; i++) {
            int idx = tid + i * 256;
            int m = idx >> 3, kk = idx & 7;
            float v = (k0 + kk < K) ? A[(size_t)(m0 + m) * K + k0 + kk] : 0.f;
            As[kk][m] = v;
        }
        // W tile: 64x8
#pragma unroll
        for (int i = 0; i < 2; i++) {
            int idx = tid + i * 256;
            int n = idx >> 3, kk = idx & 7;
            float v = (k0 + kk < K) ? W[(size_t)(n0 + n) * K + k0 + kk] : 0.f;
            Bs[kk][n] = v;
        }
        __syncthreads();
#pragma unroll
        for (int kk = 0; kk < GBK; kk++) {
            float a[8], b[4];
#pragma unroll
            for (int i = 0; i < 8; i++) a[i] = As[kk][ty * 8 + i];
#pragma unroll
            for (int j = 0; j < 4; j++) b[j] = Bs[kk][tx * 4 + j];
#pragma unroll
            for (int i = 0; i < 8; i++)
#pragma unroll
                for (int j = 0; j < 4; j++) acc[i][j] = fmaf(a[i], b[j], acc[i][j]);
        }
        __syncthreads();
    }

    float bb[4];
#pragma unroll
    for (int j = 0; j < 4; j++) bb[j] = bias[n0 + tx * 4 + j];
#pragma unroll
    for (int i = 0; i < 8; i++) {
        size_t row = (size_t)(m0 + ty * 8 + i) * N + n0 + tx * 4;
#pragma unroll
        for (int j = 0; j < 4; j++) C[row + j] = acc[i][j] + bb[j];
    }
}

// ---------------- persistent GRU recurrence -------------------------------
// Grid: 8 batch-groups (32 batch each) x 16 unit-groups (16 units each) = 128 CTAs.
// Each CTA holds its W_hh slice (48 rows x 256) in smem for all 512 steps.
// 128 threads: tid = jl*8 + bgr; thread owns unit (j0+jl) for 4 batches
// b_local = bgr + 8*i (stride-8 -> conflict-free smem row access).
#define RGB 8
#define RGJ 16
#define RBT 32
#define RJT 16
#define RTHREADS 128
#define RGRID (RGB*RGJ)
#define HPAD 260   // padded row stride (floats); 260 % 32 == 4 -> banks 4*row

__global__ __launch_bounds__(RTHREADS, 1) void gru_rec_kernel(
    const float* __restrict__ W_hh, const float* __restrict__ b_hh, int layer0)
{
    extern __shared__ float smem[];
    float* Ws = smem;                       // [3*RJT][HPAD]
    float* hs = smem + 3 * RJT * HPAD;      // [RBT][HPAD]

    const int tid = threadIdx.x;
    const int bg = blockIdx.x & (RGB - 1);
    const int jg = blockIdx.x / RGB;
    const int b0 = bg * RBT;
    const int j0 = jg * RJT;

    // Load W_hh slice once: rows (g*256 + j0 + jl), g in {0,1,2}
    for (int idx = tid; idx < 3 * RJT * 64; idx += RTHREADS) {
        int row = idx >> 6;          // 0..47, row = g*16 + jl
        int kq = idx & 63;
        int g = row / RJT, jl = row % RJT;
        float4 v = *(const float4*)&W_hh[((size_t)(g * HH + j0 + jl)) * HH + kq * 4];
        *(float4*)&Ws[row * HPAD + kq * 4] = v;
    }

    const int jl = tid >> 3;
    const int bgr = tid & 7;
    const int jglob = j0 + jl;
    const float bhr = b_hh[jglob];
    const float bhz = b_hh[HH + jglob];
    const float bhn = b_hh[2 * HH + jglob];
    const float* wr = &Ws[(0 * RJT + jl) * HPAD];
    const float* wz = &Ws[(1 * RJT + jl) * HPAD];
    const float* wn = &Ws[(2 * RJT + jl) * HPAD];

    for (int s = 0; s < TT; s++) {
        // ---- load h_{s-1} tile (32 batches x 256) into smem ----
        if (s == 0) {
            float4 z4 = make_float4(0.f, 0.f, 0.f, 0.f);
            for (int idx = tid; idx < RBT * 64; idx += RTHREADS)
                *(float4*)&hs[(idx >> 6) * HPAD + (idx & 63) * 4] = z4;
        } else if (layer0) {
            for (int idx = tid; idx < RBT * 64; idx += RTHREADS) {
                int b = idx >> 6, kq = idx & 63;
                float4 v = __ldcg((const float4*)&g_out0[(((size_t)(b0 + b)) * TT + (s - 1)) * HH + kq * 4]);
                *(float4*)&hs[b * HPAD + kq * 4] = v;
            }
        } else {
            const float* src = g_hbuf[s & 1];
            for (int idx = tid; idx < RBT * 64; idx += RTHREADS) {
                int b = idx >> 6, kq = idx & 63;
                float4 v = __ldcg((const float4*)&src[(size_t)(b0 + b) * HH + kq * 4]);
                *(float4*)&hs[b * HPAD + kq * 4] = v;
            }
        }
        __syncthreads();

        // ---- prefetch xg for this step's 4 (b, j) outputs ----
        float xr[4], xz[4], xn[4];
#pragma unroll
        for (int i = 0; i < 4; i++) {
            int b = b0 + bgr + 8 * i;
            const float* xgp = &g_xg[((size_t)b * TT + s) * G3];
            xr[i] = __ldg(&xgp[jglob]);
            xz[i] = __ldg(&xgp[HH + jglob]);
            xn[i] = __ldg(&xgp[2 * HH + jglob]);
        }

        // ---- 3-gate dot products over k=0..255 ----
        float ar[4] = {0.f, 0.f, 0.f, 0.f};
        float az[4] = {0.f, 0.f, 0.f, 0.f};
        float an[4] = {0.f, 0.f, 0.f, 0.f};
#pragma unroll 4
        for (int kq = 0; kq < 64; kq++) {
            float4 w_r = *(const float4*)&wr[kq * 4];
            float4 w_z = *(const float4*)&wz[kq * 4];
            float4 w_n = *(const float4*)&wn[kq * 4];
#pragma unroll
            for (int i = 0; i < 4; i++) {
                float4 hv = *(const float4*)&hs[(bgr + 8 * i) * HPAD + kq * 4];
                ar[i] = fmaf(hv.x, w_r.x, fmaf(hv.y, w_r.y, fmaf(hv.z, w_r.z, fmaf(hv.w, w_r.w, ar[i]))));
                az[i] = fmaf(hv.x, w_z.x, fmaf(hv.y, w_z.y, fmaf(hv.z, w_z.z, fmaf(hv.w, w_z.w, az[i]))));
                an[i] = fmaf(hv.x, w_n.x, fmaf(hv.y, w_n.y, fmaf(hv.z, w_n.z, fmaf(hv.w, w_n.w, an[i]))));
            }
        }

        // ---- gates + state update ----
#pragma unroll
        for (int i = 0; i < 4; i++) {
            int bl = bgr + 8 * i;
            int b = b0 + bl;
            float hp = hs[bl * HPAD + jglob];
            float r = 1.f / (1.f + expf(-(xr[i] + bhr + ar[i])));
            float z = 1.f / (1.f + expf(-(xz[i] + bhz + az[i])));
            float hn = bhn + an[i];
            float nn = tanhf(xn[i] + r * hn);
            float hnew = (1.f - z) * nn + z * hp;
            if (layer0)
                g_out0[((size_t)b * TT + s) * HH + jglob] = hnew;
            else
                g_hbuf[(s + 1) & 1][(size_t)b * HH + jglob] = hnew;
        }

        // ---- grid barrier (all 128 CTAs co-resident) ----
        __syncthreads();
        if (tid == 0) {
            __threadfence();
            atomicAdd(&g_cnt[s], 1u);
            while (*(volatile unsigned*)&g_cnt[s] < RGRID) { }
        }
        __syncthreads();
    }
}

// ---------------------------------------------------------------------------
extern "C" void kernel_launch(void* const* d_in, const int* in_sizes, int n_in,
                              void* d_out, int out_size)
{
    const float* x     = (const float*)d_in[0];
    const float* W_ih0 = (const float*)d_in[1];
    const float* W_hh0 = (const float*)d_in[2];
    const float* b_ih0 = (const float*)d_in[3];
    const float* b_hh0 = (const float*)d_in[4];
    const float* W_ih1 = (const float*)d_in[5];
    const float* W_hh1 = (const float*)d_in[6];
    const float* b_ih1 = (const float*)d_in[7];
    const float* b_hh1 = (const float*)d_in[8];
    const float* fc_W  = (const float*)d_in[9];
    const float* fc_b  = (const float*)d_in[10];
    float* out = (float*)d_out;

    float *xg, *out0, *hbuf;
    cudaGetSymbolAddress((void**)&xg,   g_xg);
    cudaGetSymbolAddress((void**)&out0, g_out0);
    cudaGetSymbolAddress((void**)&hbuf, g_hbuf);

    const int rec_smem = (3 * RJT * HPAD + RBT * HPAD) * (int)sizeof(float); // 83200 B
    cudaFuncSetAttribute(gru_rec_kernel, cudaFuncAttributeMaxDynamicSharedMemorySize, rec_smem);

    // layer 0 input preactivations: [BT,75] @ [768,75]^T
    gemm_bias_kernel<<<dim3(BT / GBM, G3 / GBN), 256>>>(x, W_ih0, b_ih0, xg, BT, G3, INDIM);
    // layer 0 recurrence -> g_out0
    zero_cnt_kernel<<<1, 512>>>();
    gru_rec_kernel<<<RGRID, RTHREADS, rec_smem>>>(W_hh0, b_hh0, 1);
    // layer 1 input preactivations: [BT,256] @ [768,256]^T
    gemm_bias_kernel<<<dim3(BT / GBM, G3 / GBN), 256>>>(out0, W_ih1, b_ih1, xg, BT, G3, HH);
    // layer 1 recurrence -> g_hbuf[0] holds h_T
    zero_cnt_kernel<<<1, 512>>>();
    gru_rec_kernel<<<RGRID, RTHREADS, rec_smem>>>(W_hh1, b_hh1, 0);
    // FC: [256,256] @ [256,256]^T + b
    gemm_bias_kernel<<<dim3(BB / GBM, HH / GBN), 256>>>(hbuf, fc_W, fc_b, out, BB, HH, HH);
}

// round 2
// speedup vs baseline: 1.1104x; 1.1104x over previous
#include <cuda_runtime.h>
#include <math.h>

// Problem dims
#define BB 256
#define TT 512
#define HH 256
#define G3 768          // 3*H
#define INDIM 75
#define BT (BB*TT)      // 131072

// ---------------- scratch (device globals; no allocations allowed) ---------
__device__ float g_xg[(size_t)BB * TT * G3];     // input-gate preactivations (reused per layer)
__device__ float g_out0[(size_t)BB * TT * HH];   // layer-0 hidden states
__device__ float g_hbuf[2][BB * HH];             // layer-1 h ping-pong
__device__ unsigned g_cnt[TT];                   // per-step arrival counters

// ---------------- tiny kernel: reset barrier counters ----------------------
__global__ void zero_cnt_kernel() {
    int t = threadIdx.x;
    if (t < TT) g_cnt[t] = 0u;
}

// ---------------- TF32 tensor-core GEMM: C = A[M,K] @ W[N,K]^T + bias ------
// BM=128, BN=64, BK=16. 256 threads = 8 warps in 4(m) x 2(n); warp tile 32x32.
// mma.sync.aligned.m16n8k8.row.col.f32.tf32.tf32.f32
#define TBM 128
#define TBN 64
#define TBK 16
#define TPAD 20   // smem row stride (floats); (20*g + t) mod 32 distinct -> conflict-free

__device__ __forceinline__ unsigned f2tf32(float v) {
    unsigned u;
    asm("cvt.rna.tf32.f32 %0, %1;" : "=r"(u) : "f"(v));
    return u;
}

__device__ __forceinline__ void mma_tf32(float c[4], const unsigned a[4], unsigned b0, unsigned b1) {
    asm volatile(
        "mma.sync.aligned.m16n8k8.row.col.f32.tf32.tf32.f32 "
        "{%0,%1,%2,%3}, {%4,%5,%6,%7}, {%8,%9}, {%0,%1,%2,%3};"
        : "+f"(c[0]), "+f"(c[1]), "+f"(c[2]), "+f"(c[3])
        : "r"(a[0]), "r"(a[1]), "r"(a[2]), "r"(a[3]), "r"(b0), "r"(b1));
}

__global__ __launch_bounds__(256) void tf32_gemm_bias_kernel(
    const float* __restrict__ A, const float* __restrict__ W,
    const float* __restrict__ bias, float* __restrict__ C,
    int M, int N, int K)
{
    __shared__ unsigned As[TBM * TPAD];
    __shared__ unsigned Bs[TBN * TPAD];

    const int tid = threadIdx.x;
    const int wid = tid >> 5, lane = tid & 31;
    const int g = lane >> 2, t = lane & 3;
    const int wm = wid & 3, wn = wid >> 2;
    const int m0 = blockIdx.y * TBM;
    const int n0 = blockIdx.x * TBN;

    float acc[2][4][4];
#pragma unroll
    for (int mt = 0; mt < 2; mt++)
#pragma unroll
        for (int nt = 0; nt < 4; nt++)
#pragma unroll
            for (int i = 0; i < 4; i++) acc[mt][nt][i] = 0.f;

    // global-load assignments
    const int am = tid >> 4;          // 0..15 (row within tile, +16*i)
    const int ak = tid & 15;          // k within tile
    const int bn = tid >> 2;          // 0..63
    const int bk4 = (tid & 3) * 4;    // k base within tile

    float ra[8], rb[4];
    const int nk = (K + TBK - 1) / TBK;

    // prefetch tile 0
    {
        const int kb = 0;
#pragma unroll
        for (int i = 0; i < 8; i++) {
            int m = am + i * 16;
            ra[i] = (kb + ak < K) ? __ldg(&A[(size_t)(m0 + m) * K + kb + ak]) : 0.f;
        }
#pragma unroll
        for (int i = 0; i < 4; i++) {
            int k = kb + bk4 + i;
            rb[i] = (k < K) ? __ldg(&W[(size_t)(n0 + bn) * K + k]) : 0.f;
        }
    }

    for (int kt = 0; kt < nk; kt++) {
        // store current tile to smem (convert to tf32)
#pragma unroll
        for (int i = 0; i < 8; i++) As[(am + i * 16) * TPAD + ak] = f2tf32(ra[i]);
#pragma unroll
        for (int i = 0; i < 4; i++) Bs[bn * TPAD + bk4 + i] = f2tf32(rb[i]);
        __syncthreads();

        // prefetch next tile
        if (kt + 1 < nk) {
            const int kb = (kt + 1) * TBK;
#pragma unroll
            for (int i = 0; i < 8; i++) {
                int m = am + i * 16;
                ra[i] = (kb + ak < K) ? __ldg(&A[(size_t)(m0 + m) * K + kb + ak]) : 0.f;
            }
#pragma unroll
            for (int i = 0; i < 4; i++) {
                int k = kb + bk4 + i;
                rb[i] = (k < K) ? __ldg(&W[(size_t)(n0 + bn) * K + k]) : 0.f;
            }
        }

        // compute: 2 k-steps of k=8
#pragma unroll
        for (int ks = 0; ks < 2; ks++) {
            const int k = ks * 8;
            unsigned af[2][4];
#pragma unroll
            for (int mt = 0; mt < 2; mt++) {
                int row = wm * 32 + mt * 16;
                af[mt][0] = As[(row + g) * TPAD + k + t];
                af[mt][1] = As[(row + g + 8) * TPAD + k + t];
                af[mt][2] = As[(row + g) * TPAD + k + t + 4];
                af[mt][3] = As[(row + g + 8) * TPAD + k + t + 4];
            }
#pragma unroll
            for (int nt = 0; nt < 4; nt++) {
                int col = wn * 32 + nt * 8;
                unsigned b0 = Bs[(col + g) * TPAD + k + t];
                unsigned b1 = Bs[(col + g) * TPAD + k + t + 4];
#pragma unroll
                for (int mt = 0; mt < 2; mt++) mma_tf32(acc[mt][nt], af[mt], b0, b1);
            }
        }
        __syncthreads();
    }

    // epilogue with bias
#pragma unroll
    for (int mt = 0; mt < 2; mt++) {
#pragma unroll
        for (int nt = 0; nt < 4; nt++) {
            int row = m0 + wm * 32 + mt * 16 + g;
            int col = n0 + wn * 32 + nt * 8 + 2 * t;
            float b0 = bias[col], b1 = bias[col + 1];
            C[(size_t)row * N + col]           = acc[mt][nt][0] + b0;
            C[(size_t)row * N + col + 1]       = acc[mt][nt][1] + b1;
            C[(size_t)(row + 8) * N + col]     = acc[mt][nt][2] + b0;
            C[(size_t)(row + 8) * N + col + 1] = acc[mt][nt][3] + b1;
        }
    }
}

// ---------------- fp32 GEMM (kept for the tiny FC) -------------------------
#define GBM 128
#define GBN 64
#define GBK 8
__global__ __launch_bounds__(256) void gemm_bias_kernel(
    const float* __restrict__ A, const float* __restrict__ W,
    const float* __restrict__ bias, float* __restrict__ C,
    int M, int N, int K)
{
    __shared__ float As[GBK][GBM];
    __shared__ float Bs[GBK][GBN + 4];

    int tid = threadIdx.x;
    int tx = tid & 15;
    int ty = tid >> 4;
    int m0 = blockIdx.x * GBM;
    int n0 = blockIdx.y * GBN;

    float acc[8][4];
#pragma unroll
    for (int i = 0; i < 8; i++)
#pragma unroll
        for (int j = 0; j < 4; j++) acc[i][j] = 0.f;

    for (int k0 = 0; k0 < K; k0 += GBK) {
#pragma unroll
        for (int i = 0; i < 4; i++) {
            int idx = tid + i * 256;
            int m = idx >> 3, kk = idx & 7;
            float v = (k0 + kk < K) ? A[(size_t)(m0 + m) * K + k0 + kk] : 0.f;
            As[kk][m] = v;
        }
#pragma unroll
        for (int i = 0; i < 2; i++) {
            int idx = tid + i * 256;
            int n = idx >> 3, kk = idx & 7;
            float v = (k0 + kk < K) ? W[(size_t)(n0 + n) * K + k0 + kk] : 0.f;
            Bs[kk][n] = v;
        }
        __syncthreads();
#pragma unroll
        for (int kk = 0; kk < GBK; kk++) {
            float a[8], b[4];
#pragma unroll
            for (int i = 0; i < 8; i++) a[i] = As[kk][ty * 8 + i];
#pragma unroll
            for (int j = 0; j < 4; j++) b[j] = Bs[kk][tx * 4 + j];
#pragma unroll
            for (int i = 0; i < 8; i++)
#pragma unroll
                for (int j = 0; j < 4; j++) acc[i][j] = fmaf(a[i], b[j], acc[i][j]);
        }
        __syncthreads();
    }

    float bb[4];
#pragma unroll
    for (int j = 0; j < 4; j++) bb[j] = bias[n0 + tx * 4 + j];
#pragma unroll
    for (int i = 0; i < 8; i++) {
        size_t row = (size_t)(m0 + ty * 8 + i) * N + n0 + tx * 4;
#pragma unroll
        for (int j = 0; j < 4; j++) C[row + j] = acc[i][j] + bb[j];
    }
}

// ---------------- persistent GRU recurrence (unchanged) --------------------
#define RGB 8
#define RGJ 16
#define RBT 32
#define RJT 16
#define RTHREADS 128
#define RGRID (RGB*RGJ)
#define HPAD 260

__global__ __launch_bounds__(RTHREADS, 1) void gru_rec_kernel(
    const float* __restrict__ W_hh, const float* __restrict__ b_hh, int layer0)
{
    extern __shared__ float smem[];
    float* Ws = smem;                       // [3*RJT][HPAD]
    float* hs = smem + 3 * RJT * HPAD;      // [RBT][HPAD]

    const int tid = threadIdx.x;
    const int bg = blockIdx.x & (RGB - 1);
    const int jg = blockIdx.x / RGB;
    const int b0 = bg * RBT;
    const int j0 = jg * RJT;

    for (int idx = tid; idx < 3 * RJT * 64; idx += RTHREADS) {
        int row = idx >> 6;
        int kq = idx & 63;
        int g = row / RJT, jl = row % RJT;
        float4 v = *(const float4*)&W_hh[((size_t)(g * HH + j0 + jl)) * HH + kq * 4];
        *(float4*)&Ws[row * HPAD + kq * 4] = v;
    }

    const int jl = tid >> 3;
    const int bgr = tid & 7;
    const int jglob = j0 + jl;
    const float bhr = b_hh[jglob];
    const float bhz = b_hh[HH + jglob];
    const float bhn = b_hh[2 * HH + jglob];
    const float* wr = &Ws[(0 * RJT + jl) * HPAD];
    const float* wz = &Ws[(1 * RJT + jl) * HPAD];
    const float* wn = &Ws[(2 * RJT + jl) * HPAD];

    for (int s = 0; s < TT; s++) {
        if (s == 0) {
            float4 z4 = make_float4(0.f, 0.f, 0.f, 0.f);
            for (int idx = tid; idx < RBT * 64; idx += RTHREADS)
                *(float4*)&hs[(idx >> 6) * HPAD + (idx & 63) * 4] = z4;
        } else if (layer0) {
            for (int idx = tid; idx < RBT * 64; idx += RTHREADS) {
                int b = idx >> 6, kq = idx & 63;
                float4 v = __ldcg((const float4*)&g_out0[(((size_t)(b0 + b)) * TT + (s - 1)) * HH + kq * 4]);
                *(float4*)&hs[b * HPAD + kq * 4] = v;
            }
        } else {
            const float* src = g_hbuf[s & 1];
            for (int idx = tid; idx < RBT * 64; idx += RTHREADS) {
                int b = idx >> 6, kq = idx & 63;
                float4 v = __ldcg((const float4*)&src[(size_t)(b0 + b) * HH + kq * 4]);
                *(float4*)&hs[b * HPAD + kq * 4] = v;
            }
        }
        __syncthreads();

        float xr[4], xz[4], xn[4];
#pragma unroll
        for (int i = 0; i < 4; i++) {
            int b = b0 + bgr + 8 * i;
            const float* xgp = &g_xg[((size_t)b * TT + s) * G3];
            xr[i] = __ldg(&xgp[jglob]);
            xz[i] = __ldg(&xgp[HH + jglob]);
            xn[i] = __ldg(&xgp[2 * HH + jglob]);
        }

        float ar[4] = {0.f, 0.f, 0.f, 0.f};
        float az[4] = {0.f, 0.f, 0.f, 0.f};
        float an[4] = {0.f, 0.f, 0.f, 0.f};
#pragma unroll 4
        for (int kq = 0; kq < 64; kq++) {
            float4 w_r = *(const float4*)&wr[kq * 4];
            float4 w_z = *(const float4*)&wz[kq * 4];
            float4 w_n = *(const float4*)&wn[kq * 4];
#pragma unroll
            for (int i = 0; i < 4; i++) {
                float4 hv = *(const float4*)&hs[(bgr + 8 * i) * HPAD + kq * 4];
                ar[i] = fmaf(hv.x, w_r.x, fmaf(hv.y, w_r.y, fmaf(hv.z, w_r.z, fmaf(hv.w, w_r.w, ar[i]))));
                az[i] = fmaf(hv.x, w_z.x, fmaf(hv.y, w_z.y, fmaf(hv.z, w_z.z, fmaf(hv.w, w_z.w, az[i]))));
                an[i] = fmaf(hv.x, w_n.x, fmaf(hv.y, w_n.y, fmaf(hv.z, w_n.z, fmaf(hv.w, w_n.w, an[i]))));
            }
        }

#pragma unroll
        for (int i = 0; i < 4; i++) {
            int bl = bgr + 8 * i;
            int b = b0 + bl;
            float hp = hs[bl * HPAD + jglob];
            float r = 1.f / (1.f + expf(-(xr[i] + bhr + ar[i])));
            float z = 1.f / (1.f + expf(-(xz[i] + bhz + az[i])));
            float hn = bhn + an[i];
            float nn = tanhf(xn[i] + r * hn);
            float hnew = (1.f - z) * nn + z * hp;
            if (layer0)
                g_out0[((size_t)b * TT + s) * HH + jglob] = hnew;
            else
                g_hbuf[(s + 1) & 1][(size_t)b * HH + jglob] = hnew;
        }

        __syncthreads();
        if (tid == 0) {
            __threadfence();
            atomicAdd(&g_cnt[s], 1u);
            while (*(volatile unsigned*)&g_cnt[s] < RGRID) { }
        }
        __syncthreads();
    }
}

// ---------------------------------------------------------------------------
extern "C" void kernel_launch(void* const* d_in, const int* in_sizes, int n_in,
                              void* d_out, int out_size)
{
    const float* x     = (const float*)d_in[0];
    const float* W_ih0 = (const float*)d_in[1];
    const float* W_hh0 = (const float*)d_in[2];
    const float* b_ih0 = (const float*)d_in[3];
    const float* b_hh0 = (const float*)d_in[4];
    const float* W_ih1 = (const float*)d_in[5];
    const float* W_hh1 = (const float*)d_in[6];
    const float* b_ih1 = (const float*)d_in[7];
    const float* b_hh1 = (const float*)d_in[8];
    const float* fc_W  = (const float*)d_in[9];
    const float* fc_b  = (const float*)d_in[10];
    float* out = (float*)d_out;

    float *xg, *out0, *hbuf;
    cudaGetSymbolAddress((void**)&xg,   g_xg);
    cudaGetSymbolAddress((void**)&out0, g_out0);
    cudaGetSymbolAddress((void**)&hbuf, g_hbuf);

    const int rec_smem = (3 * RJT * HPAD + RBT * HPAD) * (int)sizeof(float);
    cudaFuncSetAttribute(gru_rec_kernel, cudaFuncAttributeMaxDynamicSharedMemorySize, rec_smem);

    // layer 0 input preactivations: [BT,75] @ [768,75]^T   (TF32 tensor cores)
    tf32_gemm_bias_kernel<<<dim3(G3 / TBN, BT / TBM), 256>>>(x, W_ih0, b_ih0, xg, BT, G3, INDIM);
    // layer 0 recurrence -> g_out0
    zero_cnt_kernel<<<1, 512>>>();
    gru_rec_kernel<<<RGRID, RTHREADS, rec_smem>>>(W_hh0, b_hh0, 1);
    // layer 1 input preactivations: [BT,256] @ [768,256]^T (TF32 tensor cores)
    tf32_gemm_bias_kernel<<<dim3(G3 / TBN, BT / TBM), 256>>>(out0, W_ih1, b_ih1, xg, BT, G3, HH);
    // layer 1 recurrence -> g_hbuf
    zero_cnt_kernel<<<1, 512>>>();
    gru_rec_kernel<<<RGRID, RTHREADS, rec_smem>>>(W_hh1, b_hh1, 0);
    // FC: [256,256] @ [256,256]^T + b (fp32, tiny)
    gemm_bias_kernel<<<dim3(BB / GBM, HH / GBN), 256>>>(hbuf, fc_W, fc_b, out, BB, HH, HH);
}